// round 11
// baseline (speedup 1.0000x reference)
#include <cuda_runtime.h>
#include <cuda_fp16.h>
#include <cstdint>

#define INPUT_DIM 1024
#define DAY_EMB   8
#define PRED_LEN  96
#define HIDDEN    512
#define BATCH     4096
#define W1_ROWS   (INPUT_DIM + DAY_EMB)

#define BM 128
#define BN 128
#define BK 32
#define KCH (INPUT_DIM / BK)     // 32
#define NT (HIDDEN / BN)         // 4
#define MT (BATCH / BM)          // 32
#define THREADS 256
#define STAGES 5

// smem per stage (uint4 units): A = 128 rows * 5 (4 data + 1 pad)
//                               B = 32 rows * 17 (16 data + 1 pad)
#define A_PI4  5
#define B_PI4  17
#define A_I4   (BM * A_PI4)          // 640
#define B_I4   (BK * B_PI4)          // 544
#define STG_I4 (A_I4 + B_I4)         // 1184 (18944 B/stage)

// ---------------- scratch ----------------------------------------------------
__device__ __half g_xh[(size_t)BATCH * INPUT_DIM];
__device__ __half g_W1h[(size_t)PRED_LEN * INPUT_DIM * HIDDEN];
__device__ float  g_bias[PRED_LEN * HIDDEN];
__device__ float  g_part[NT * BATCH * PRED_LEN];

// ---------------- helpers ----------------------------------------------------
__device__ __forceinline__ uint32_t smem_u32(const void* p) {
    uint32_t a;
    asm("{ .reg .u64 t; cvta.to.shared.u64 t, %1; cvt.u32.u64 %0, t; }" : "=r"(a) : "l"(p));
    return a;
}
#define CP_ASYNC16(dst, src) \
    asm volatile("cp.async.cg.shared.global [%0], [%1], 16;" \
        :: "r"(dst), "l"(src) : "memory")
#define CP_COMMIT() asm volatile("cp.async.commit_group;" ::: "memory")
#define CP_WAIT3()  asm volatile("cp.async.wait_group 3;" ::: "memory")

#define LDMX4(r0, r1, r2, r3, addr) \
    asm volatile("ldmatrix.sync.aligned.m8n8.x4.shared.b16 {%0,%1,%2,%3}, [%4];" \
        : "=r"(r0), "=r"(r1), "=r"(r2), "=r"(r3) : "r"(addr))
#define LDMX4T(r0, r1, r2, r3, addr) \
    asm volatile("ldmatrix.sync.aligned.m8n8.x4.trans.shared.b16 {%0,%1,%2,%3}, [%4];" \
        : "=r"(r0), "=r"(r1), "=r"(r2), "=r"(r3) : "r"(addr))

__device__ __forceinline__ void mma_f16(float* d, const uint32_t* a, uint32_t b0, uint32_t b1) {
    asm volatile(
        "mma.sync.aligned.m16n8k16.row.col.f32.f16.f16.f32 "
        "{%0,%1,%2,%3}, {%4,%5,%6,%7}, {%8,%9}, {%0,%1,%2,%3};"
        : "+f"(d[0]), "+f"(d[1]), "+f"(d[2]), "+f"(d[3])
        : "r"(a[0]), "r"(a[1]), "r"(a[2]), "r"(a[3]), "r"(b0), "r"(b1));
}

// ---------------------------------------------------------------------------
// prep kernels
// ---------------------------------------------------------------------------
__global__ void bias_kernel(const float* __restrict__ day_emb,
                            const float* __restrict__ W1,
                            const float* __restrict__ b1) {
    int p = blockIdx.x, h = threadIdx.x;
    const float* w = W1 + (size_t)p * W1_ROWS * HIDDEN + (size_t)INPUT_DIM * HIDDEN;
    float s = b1[p * HIDDEN + h];
    #pragma unroll
    for (int e = 0; e < DAY_EMB; ++e)
        s += day_emb[p * DAY_EMB + e] * w[e * HIDDEN + h];
    g_bias[p * HIDDEN + h] = s;
}

__global__ void conv_x_kernel(const float* __restrict__ x) {
    int i = blockIdx.x * blockDim.x + threadIdx.x;     // float4 group
    const int total = BATCH * INPUT_DIM / 4;
    if (i < total) {
        float4 v = reinterpret_cast<const float4*>(x)[i];
        __half2 h0 = __floats2half2_rn(v.x, v.y);
        __half2 h1 = __floats2half2_rn(v.z, v.w);
        uint2 u;
        u.x = *reinterpret_cast<uint32_t*>(&h0);
        u.y = *reinterpret_cast<uint32_t*>(&h1);
        reinterpret_cast<uint2*>(g_xh)[i] = u;
    }
}

__global__ void conv_w_kernel(const float* __restrict__ W1) {
    long long i = (long long)blockIdx.x * blockDim.x + threadIdx.x;   // float4 group
    const long long total = (long long)PRED_LEN * INPUT_DIM * HIDDEN / 4;
    if (i < total) {
        long long e = i * 4;
        int p = (int)(e / ((long long)INPUT_DIM * HIDDEN));
        int rem = (int)(e - (long long)p * INPUT_DIM * HIDDEN);
        int k = rem / HIDDEN, n = rem % HIDDEN;
        const float* src = W1 + (size_t)p * W1_ROWS * HIDDEN + (size_t)k * HIDDEN + n;
        float4 v = *reinterpret_cast<const float4*>(src);
        __half2 h0 = __floats2half2_rn(v.x, v.y);
        __half2 h1 = __floats2half2_rn(v.z, v.w);
        uint2 u;
        u.x = *reinterpret_cast<uint32_t*>(&h0);
        u.y = *reinterpret_cast<uint32_t*>(&h1);
        reinterpret_cast<uint2*>(g_W1h)[i] = u;
    }
}

// ---------------------------------------------------------------------------
// fused fp16 GEMM (x @ W1x[p]) + bias + ReLU + dot(W2[p]) -> partials
//   grid (NT, MT, PRED_LEN); 256 thr = 8 warps (4m x 2n), warp tile 32x64
//   BK=32, 5-stage cp.async (wait_group 3), ONE barrier/iter, 2 CTAs/SM
// ---------------------------------------------------------------------------
__global__ void __launch_bounds__(THREADS, 2)
mlp_gemm_kernel(const float* __restrict__ W2) {
    extern __shared__ uint4 sm4[];                   // [STAGES][STG_I4]
    __shared__ float cs[BN], ws[BN], red[2][BM];

    const int nt = blockIdx.x, mt = blockIdx.y, p = blockIdx.z;
    const int tid = threadIdx.x, lane = tid & 31, warp = tid >> 5;
    const int wm = warp >> 1, wn = warp & 1;         // 4 x 2
    const int r = lane >> 2, cc = lane & 3;
    const int m0 = mt * BM, n0 = nt * BN;

    const uint32_t smb = smem_u32(sm4);

    // ---- cp.async staging mapping (BK=32) ----
    const int ra = tid >> 2, ca = tid & 3;           // A: rows ra, ra+64; i4 col ca
    const int rb = tid >> 3, cb = tid & 7;           // B: row rb; i4 cols cb, cb+8
    const __half* Agp = g_xh + (size_t)(m0 + ra) * INPUT_DIM + ca * 8;
    const __half* Bgp = g_W1h + ((size_t)p * INPUT_DIM + rb) * HIDDEN + n0 + cb * 8;

    auto issue_stage = [&](int s, int c) {
        const uint32_t st = smb + (uint32_t)(s * STG_I4) * 16;
        const __half* ag = Agp + c * BK;
        CP_ASYNC16(st + (uint32_t)(ra * A_PI4 + ca) * 16, ag);
        CP_ASYNC16(st + (uint32_t)((ra + 64) * A_PI4 + ca) * 16, ag + (size_t)64 * INPUT_DIM);
        const __half* bg = Bgp + (size_t)c * BK * HIDDEN;
        const uint32_t bst = st + (uint32_t)(A_I4 + rb * B_PI4 + cb) * 16;
        CP_ASYNC16(bst, bg);
        CP_ASYNC16(bst + 8 * 16, bg + 64);
    };

    // start the pipeline before anything else touches memory
    issue_stage(0, 0); CP_COMMIT();
    issue_stage(1, 1); CP_COMMIT();
    issue_stage(2, 2); CP_COMMIT();
    issue_stage(3, 3); CP_COMMIT();

    if (tid < BN) {
        cs[tid] = g_bias[p * HIDDEN + n0 + tid];
        ws[tid] = W2[p * HIDDEN + n0 + tid];
    }

    float acc[2][8][4];
    #pragma unroll
    for (int mi = 0; mi < 2; ++mi)
        #pragma unroll
        for (int ni = 0; ni < 8; ++ni)
            #pragma unroll
            for (int q = 0; q < 4; ++q) acc[mi][ni][q] = 0.0f;

    const int lrow = lane & 15, lhi = lane >> 4;

    for (int c = 0; c < KCH; ++c) {
        const int s = c % STAGES;
        CP_WAIT3();
        __syncthreads();                 // single barrier per iteration

        if (c + 4 < KCH) issue_stage((c + 4) % STAGES, c + 4);
        CP_COMMIT();

        const uint32_t Ab = smb + (uint32_t)(s * STG_I4) * 16;
        const uint32_t Bb = Ab + (uint32_t)A_I4 * 16;
        #pragma unroll
        for (int kb = 0; kb < 2; ++kb) {
            uint32_t a[2][4], b[4][4];
            #pragma unroll
            for (int mi = 0; mi < 2; ++mi) {
                uint32_t addr = Ab + (uint32_t)((wm * 32 + mi * 16 + lrow) * A_PI4 + kb * 2 + lhi) * 16;
                LDMX4(a[mi][0], a[mi][1], a[mi][2], a[mi][3], addr);
            }
            #pragma unroll
            for (int nj = 0; nj < 4; ++nj) {
                uint32_t addr = Bb + (uint32_t)((kb * 16 + lrow) * B_PI4) * 16
                              + (uint32_t)(wn * 128 + nj * 32 + lhi * 16);
                LDMX4T(b[nj][0], b[nj][1], b[nj][2], b[nj][3], addr);
            }
            #pragma unroll
            for (int mi = 0; mi < 2; ++mi)
                #pragma unroll
                for (int ni = 0; ni < 8; ++ni) {
                    const uint32_t* bp = b[ni >> 1];
                    uint32_t b0 = (ni & 1) ? bp[2] : bp[0];
                    uint32_t b1 = (ni & 1) ? bp[3] : bp[1];
                    mma_f16(acc[mi][ni], a[mi], b0, b1);
                }
        }
    }

    __syncthreads();

    // ---- fused epilogue: bias + relu + W2 dot, reduce over n ----
    #pragma unroll
    for (int mi = 0; mi < 2; ++mi) {
        float rs0 = 0.0f, rs1 = 0.0f;
        #pragma unroll
        for (int ni = 0; ni < 8; ++ni) {
            int col = wn * 64 + ni * 8 + cc * 2;
            float h0 = acc[mi][ni][0] + cs[col];
            float h1 = acc[mi][ni][1] + cs[col + 1];
            float h2 = acc[mi][ni][2] + cs[col];
            float h3 = acc[mi][ni][3] + cs[col + 1];
            rs0 += fmaxf(h0, 0.0f) * ws[col] + fmaxf(h1, 0.0f) * ws[col + 1];
            rs1 += fmaxf(h2, 0.0f) * ws[col] + fmaxf(h3, 0.0f) * ws[col + 1];
        }
        #pragma unroll
        for (int off = 1; off < 4; off <<= 1) {
            rs0 += __shfl_xor_sync(0xffffffffu, rs0, off);
            rs1 += __shfl_xor_sync(0xffffffffu, rs1, off);
        }
        if ((lane & 3) == 0) {
            int row = wm * 32 + mi * 16 + r;
            red[wn][row]     = rs0;
            red[wn][row + 8] = rs1;
        }
    }
    __syncthreads();

    if (tid < BM) {
        float v = red[0][tid] + red[1][tid];
        g_part[((size_t)nt * BATCH + m0 + tid) * PRED_LEN + p] = v;
    }
}

// ---------------------------------------------------------------------------
__global__ void reduce_kernel(const float* __restrict__ b2, float* __restrict__ out) {
    int idx = blockIdx.x * blockDim.x + threadIdx.x;
    if (idx >= BATCH * PRED_LEN) return;
    int p = idx % PRED_LEN;
    float s = b2[p];
    #pragma unroll
    for (int nt = 0; nt < NT; ++nt)
        s += g_part[(size_t)nt * BATCH * PRED_LEN + idx];
    out[idx] = s;
}

// ---------------------------------------------------------------------------
extern "C" void kernel_launch(void* const* d_in, const int* in_sizes, int n_in,
                              void* d_out, int out_size) {
    const float* x       = (const float*)d_in[0];
    const float* day_emb = (const float*)d_in[1];
    const float* W1      = (const float*)d_in[2];
    const float* b1      = (const float*)d_in[3];
    const float* W2      = (const float*)d_in[4];
    const float* b2      = (const float*)d_in[5];
    float* out = (float*)d_out;

    const int SMEM = STAGES * STG_I4 * 16;   // 94720 bytes
    cudaFuncSetAttribute(mlp_gemm_kernel,
                         cudaFuncAttributeMaxDynamicSharedMemorySize, SMEM);

    bias_kernel<<<PRED_LEN, HIDDEN>>>(day_emb, W1, b1);

    int xTot = BATCH * INPUT_DIM / 4;
    conv_x_kernel<<<(xTot + 255) / 256, 256>>>(x);

    long long wTot = (long long)PRED_LEN * INPUT_DIM * HIDDEN / 4;
    conv_w_kernel<<<(int)((wTot + 255) / 256), 256>>>(W1);

    dim3 grid(NT, MT, PRED_LEN);
    mlp_gemm_kernel<<<grid, THREADS, SMEM>>>(W2);

    int total = BATCH * PRED_LEN;
    reduce_kernel<<<(total + 255) / 256, 256>>>(b2, out);
}

// round 12
// speedup vs baseline: 1.1658x; 1.1658x over previous
#include <cuda_runtime.h>
#include <cuda_fp16.h>
#include <cstdint>

#define INPUT_DIM 1024
#define DAY_EMB   8
#define PRED_LEN  96
#define HIDDEN    512
#define BATCH     4096
#define W1_ROWS   (INPUT_DIM + DAY_EMB)

#define BM 128
#define BN 128
#define BK 32
#define KCH (INPUT_DIM / BK)     // 32
#define NT (HIDDEN / BN)         // 4
#define MT (BATCH / BM)          // 32
#define THREADS 256
#define STAGES 4

// smem per stage (uint4 units): A = 128 rows * 5 (4 data + 1 pad)
//                               B = 32 rows * 17 (16 data + 1 pad)
#define A_PI4  5
#define B_PI4  17
#define A_I4   (BM * A_PI4)          // 640
#define B_I4   (BK * B_PI4)          // 544
#define STG_I4 (A_I4 + B_I4)         // 1184 (18944 B/stage)

// ---------------- scratch ----------------------------------------------------
__device__ __half g_xh[(size_t)BATCH * INPUT_DIM];
__device__ __half g_W1h[(size_t)PRED_LEN * INPUT_DIM * HIDDEN];
__device__ float  g_bias[PRED_LEN * HIDDEN];
__device__ float  g_part[NT * BATCH * PRED_LEN];

// ---------------- helpers ----------------------------------------------------
__device__ __forceinline__ uint32_t smem_u32(const void* p) {
    uint32_t a;
    asm("{ .reg .u64 t; cvta.to.shared.u64 t, %1; cvt.u32.u64 %0, t; }" : "=r"(a) : "l"(p));
    return a;
}
#define CP_ASYNC16(dst, src) \
    asm volatile("cp.async.cg.shared.global [%0], [%1], 16;" \
        :: "r"(dst), "l"(src) : "memory")
#define CP_COMMIT() asm volatile("cp.async.commit_group;" ::: "memory")
#define CP_WAIT2()  asm volatile("cp.async.wait_group 2;" ::: "memory")

#define LDMX4(r0, r1, r2, r3, addr) \
    asm volatile("ldmatrix.sync.aligned.m8n8.x4.shared.b16 {%0,%1,%2,%3}, [%4];" \
        : "=r"(r0), "=r"(r1), "=r"(r2), "=r"(r3) : "r"(addr))
#define LDMX4T(r0, r1, r2, r3, addr) \
    asm volatile("ldmatrix.sync.aligned.m8n8.x4.trans.shared.b16 {%0,%1,%2,%3}, [%4];" \
        : "=r"(r0), "=r"(r1), "=r"(r2), "=r"(r3) : "r"(addr))

__device__ __forceinline__ void mma_f16(float* d, const uint32_t* a, uint32_t b0, uint32_t b1) {
    asm volatile(
        "mma.sync.aligned.m16n8k16.row.col.f32.f16.f16.f32 "
        "{%0,%1,%2,%3}, {%4,%5,%6,%7}, {%8,%9}, {%0,%1,%2,%3};"
        : "+f"(d[0]), "+f"(d[1]), "+f"(d[2]), "+f"(d[3])
        : "r"(a[0]), "r"(a[1]), "r"(a[2]), "r"(a[3]), "r"(b0), "r"(b1));
}

// ---------------------------------------------------------------------------
// prep kernels
// ---------------------------------------------------------------------------
__global__ void bias_kernel(const float* __restrict__ day_emb,
                            const float* __restrict__ W1,
                            const float* __restrict__ b1) {
    int p = blockIdx.x, h = threadIdx.x;
    const float* w = W1 + (size_t)p * W1_ROWS * HIDDEN + (size_t)INPUT_DIM * HIDDEN;
    float s = b1[p * HIDDEN + h];
    #pragma unroll
    for (int e = 0; e < DAY_EMB; ++e)
        s += day_emb[p * DAY_EMB + e] * w[e * HIDDEN + h];
    g_bias[p * HIDDEN + h] = s;
}

__global__ void conv_x_kernel(const float* __restrict__ x) {
    int i = blockIdx.x * blockDim.x + threadIdx.x;     // float4 group
    const int total = BATCH * INPUT_DIM / 4;
    if (i < total) {
        float4 v = reinterpret_cast<const float4*>(x)[i];
        __half2 h0 = __floats2half2_rn(v.x, v.y);
        __half2 h1 = __floats2half2_rn(v.z, v.w);
        uint2 u;
        u.x = *reinterpret_cast<uint32_t*>(&h0);
        u.y = *reinterpret_cast<uint32_t*>(&h1);
        reinterpret_cast<uint2*>(g_xh)[i] = u;
    }
}

__global__ void conv_w_kernel(const float* __restrict__ W1) {
    long long i = (long long)blockIdx.x * blockDim.x + threadIdx.x;   // float4 group
    const long long total = (long long)PRED_LEN * INPUT_DIM * HIDDEN / 4;
    if (i < total) {
        long long e = i * 4;
        int p = (int)(e / ((long long)INPUT_DIM * HIDDEN));
        int rem = (int)(e - (long long)p * INPUT_DIM * HIDDEN);
        int k = rem / HIDDEN, n = rem % HIDDEN;
        const float* src = W1 + (size_t)p * W1_ROWS * HIDDEN + (size_t)k * HIDDEN + n;
        float4 v = *reinterpret_cast<const float4*>(src);
        __half2 h0 = __floats2half2_rn(v.x, v.y);
        __half2 h1 = __floats2half2_rn(v.z, v.w);
        uint2 u;
        u.x = *reinterpret_cast<uint32_t*>(&h0);
        u.y = *reinterpret_cast<uint32_t*>(&h1);
        reinterpret_cast<uint2*>(g_W1h)[i] = u;
    }
}

// ---------------------------------------------------------------------------
// fused fp16 GEMM (x @ W1x[p]) + bias + ReLU + dot(W2[p]) -> partials
//   grid (NT, MT, PRED_LEN); 256 thr = 8 warps (4m x 2n), warp tile 32x64
//   BK=32, 4-stage cp.async (wait_group 2), ONE barrier/iter, 2 CTAs/SM
// ---------------------------------------------------------------------------
__global__ void __launch_bounds__(THREADS, 2)
mlp_gemm_kernel(const float* __restrict__ W2) {
    extern __shared__ uint4 sm4[];                   // [STAGES][STG_I4]
    __shared__ float cs[BN], ws[BN], red[2][BM];

    const int nt = blockIdx.x, mt = blockIdx.y, p = blockIdx.z;
    const int tid = threadIdx.x, lane = tid & 31, warp = tid >> 5;
    const int wm = warp >> 1, wn = warp & 1;         // 4 x 2
    const int r = lane >> 2, cc = lane & 3;
    const int m0 = mt * BM, n0 = nt * BN;

    const uint32_t smb = smem_u32(sm4);

    // ---- cp.async staging mapping (BK=32) ----
    const int ra = tid >> 2, ca = tid & 3;           // A: rows ra, ra+64; i4 col ca
    const int rb = tid >> 3, cb = tid & 7;           // B: row rb; i4 cols cb, cb+8
    const __half* Agp = g_xh + (size_t)(m0 + ra) * INPUT_DIM + ca * 8;
    const __half* Bgp = g_W1h + ((size_t)p * INPUT_DIM + rb) * HIDDEN + n0 + cb * 8;

    auto issue_stage = [&](int s, int c) {
        const uint32_t st = smb + (uint32_t)(s * STG_I4) * 16;
        const __half* ag = Agp + c * BK;
        CP_ASYNC16(st + (uint32_t)(ra * A_PI4 + ca) * 16, ag);
        CP_ASYNC16(st + (uint32_t)((ra + 64) * A_PI4 + ca) * 16, ag + (size_t)64 * INPUT_DIM);
        const __half* bg = Bgp + (size_t)c * BK * HIDDEN;
        const uint32_t bst = st + (uint32_t)(A_I4 + rb * B_PI4 + cb) * 16;
        CP_ASYNC16(bst, bg);
        CP_ASYNC16(bst + 8 * 16, bg + 64);
    };

    // start the pipeline first
    issue_stage(0, 0); CP_COMMIT();
    issue_stage(1, 1); CP_COMMIT();
    issue_stage(2, 2); CP_COMMIT();

    if (tid < BN) {
        cs[tid] = g_bias[p * HIDDEN + n0 + tid];
        ws[tid] = W2[p * HIDDEN + n0 + tid];
    }

    float acc[2][8][4];
    #pragma unroll
    for (int mi = 0; mi < 2; ++mi)
        #pragma unroll
        for (int ni = 0; ni < 8; ++ni)
            #pragma unroll
            for (int q = 0; q < 4; ++q) acc[mi][ni][q] = 0.0f;

    const int lrow = lane & 15, lhi = lane >> 4;

    for (int c = 0; c < KCH; ++c) {
        const int s = c & 3;
        CP_WAIT2();
        __syncthreads();                 // single barrier per iteration

        const uint32_t Ab = smb + (uint32_t)(s * STG_I4) * 16;
        const uint32_t Bb = Ab + (uint32_t)A_I4 * 16;
        #pragma unroll
        for (int kb = 0; kb < 2; ++kb) {
            uint32_t a[2][4], b[4][4];
            #pragma unroll
            for (int mi = 0; mi < 2; ++mi) {
                uint32_t addr = Ab + (uint32_t)((wm * 32 + mi * 16 + lrow) * A_PI4 + kb * 2 + lhi) * 16;
                LDMX4(a[mi][0], a[mi][1], a[mi][2], a[mi][3], addr);
            }
            #pragma unroll
            for (int nj = 0; nj < 4; ++nj) {
                uint32_t addr = Bb + (uint32_t)((kb * 16 + lrow) * B_PI4) * 16
                              + (uint32_t)(wn * 128 + nj * 32 + lhi * 16);
                LDMX4T(b[nj][0], b[nj][1], b[nj][2], b[nj][3], addr);
            }
            // issue next stage AFTER kb=0 fragments are requested: the
            // ldmatrix->mma critical path starts immediately; staging LSU
            // work overlaps with kb=0 mma instead of preceding it.
            if (kb == 0) {
                if (c + 3 < KCH) issue_stage((c + 3) & 3, c + 3);
                CP_COMMIT();
            }
            #pragma unroll
            for (int mi = 0; mi < 2; ++mi)
                #pragma unroll
                for (int ni = 0; ni < 8; ++ni) {
                    const uint32_t* bp = b[ni >> 1];
                    uint32_t b0 = (ni & 1) ? bp[2] : bp[0];
                    uint32_t b1 = (ni & 1) ? bp[3] : bp[1];
                    mma_f16(acc[mi][ni], a[mi], b0, b1);
                }
        }
    }

    __syncthreads();

    // ---- fused epilogue: bias + relu + W2 dot, reduce over n ----
    #pragma unroll
    for (int mi = 0; mi < 2; ++mi) {
        float rs0 = 0.0f, rs1 = 0.0f;
        #pragma unroll
        for (int ni = 0; ni < 8; ++ni) {
            int col = wn * 64 + ni * 8 + cc * 2;
            float h0 = acc[mi][ni][0] + cs[col];
            float h1 = acc[mi][ni][1] + cs[col + 1];
            float h2 = acc[mi][ni][2] + cs[col];
            float h3 = acc[mi][ni][3] + cs[col + 1];
            rs0 += fmaxf(h0, 0.0f) * ws[col] + fmaxf(h1, 0.0f) * ws[col + 1];
            rs1 += fmaxf(h2, 0.0f) * ws[col] + fmaxf(h3, 0.0f) * ws[col + 1];
        }
        #pragma unroll
        for (int off = 1; off < 4; off <<= 1) {
            rs0 += __shfl_xor_sync(0xffffffffu, rs0, off);
            rs1 += __shfl_xor_sync(0xffffffffu, rs1, off);
        }
        if ((lane & 3) == 0) {
            int row = wm * 32 + mi * 16 + r;
            red[wn][row]     = rs0;
            red[wn][row + 8] = rs1;
        }
    }
    __syncthreads();

    if (tid < BM) {
        float v = red[0][tid] + red[1][tid];
        g_part[((size_t)nt * BATCH + m0 + tid) * PRED_LEN + p] = v;
    }
}

// ---------------------------------------------------------------------------
__global__ void reduce_kernel(const float* __restrict__ b2, float* __restrict__ out) {
    int idx = blockIdx.x * blockDim.x + threadIdx.x;
    if (idx >= BATCH * PRED_LEN) return;
    int p = idx % PRED_LEN;
    float s = b2[p];
    #pragma unroll
    for (int nt = 0; nt < NT; ++nt)
        s += g_part[(size_t)nt * BATCH * PRED_LEN + idx];
    out[idx] = s;
}

// ---------------------------------------------------------------------------
extern "C" void kernel_launch(void* const* d_in, const int* in_sizes, int n_in,
                              void* d_out, int out_size) {
    const float* x       = (const float*)d_in[0];
    const float* day_emb = (const float*)d_in[1];
    const float* W1      = (const float*)d_in[2];
    const float* b1      = (const float*)d_in[3];
    const float* W2      = (const float*)d_in[4];
    const float* b2      = (const float*)d_in[5];
    float* out = (float*)d_out;

    const int SMEM = STAGES * STG_I4 * 16;   // 75776 bytes
    cudaFuncSetAttribute(mlp_gemm_kernel,
                         cudaFuncAttributeMaxDynamicSharedMemorySize, SMEM);

    bias_kernel<<<PRED_LEN, HIDDEN>>>(day_emb, W1, b1);

    int xTot = BATCH * INPUT_DIM / 4;
    conv_x_kernel<<<(xTot + 255) / 256, 256>>>(x);

    long long wTot = (long long)PRED_LEN * INPUT_DIM * HIDDEN / 4;
    conv_w_kernel<<<(int)((wTot + 255) / 256), 256>>>(W1);

    dim3 grid(NT, MT, PRED_LEN);
    mlp_gemm_kernel<<<grid, THREADS, SMEM>>>(W2);

    int total = BATCH * PRED_LEN;
    reduce_kernel<<<(total + 255) / 256, 256>>>(b2, out);
}

// round 13
// speedup vs baseline: 1.2704x; 1.0897x over previous
#include <cuda_runtime.h>
#include <cuda_fp16.h>
#include <cstdint>

#define INPUT_DIM 1024
#define DAY_EMB   8
#define PRED_LEN  96
#define HIDDEN    512
#define BATCH     4096
#define W1_ROWS   (INPUT_DIM + DAY_EMB)

#define BM 128
#define BN 128
#define BK 32
#define KCH (INPUT_DIM / BK)     // 32
#define NT (HIDDEN / BN)         // 4
#define MT (BATCH / BM)          // 32
#define THREADS 256
#define STAGES 4

// smem per stage (uint4 units): A = 128 rows * 5 (4 data + 1 pad)
//                               B = 32 rows * 17 (16 data + 1 pad)
#define A_PI4  5
#define B_PI4  17
#define A_I4   (BM * A_PI4)          // 640
#define B_I4   (BK * B_PI4)          // 544
#define STG_I4 (A_I4 + B_I4)         // 1184 (18944 B/stage)

// fused prep launch geometry
#define XBLKS (BATCH * INPUT_DIM / 4 / 256)                       // 4096
#define WBLKS ((int)((long long)PRED_LEN * INPUT_DIM * HIDDEN / 4 / 256))  // 49152
#define PREP_BLKS (XBLKS + WBLKS + PRED_LEN)

// ---------------- scratch ----------------------------------------------------
__device__ __half g_xh[(size_t)BATCH * INPUT_DIM];
__device__ __half g_W1h[(size_t)PRED_LEN * INPUT_DIM * HIDDEN];
__device__ float  g_bias[PRED_LEN * HIDDEN];
__device__ float  g_part[NT * BATCH * PRED_LEN];

// ---------------- helpers ----------------------------------------------------
__device__ __forceinline__ uint32_t smem_u32(const void* p) {
    uint32_t a;
    asm("{ .reg .u64 t; cvta.to.shared.u64 t, %1; cvt.u32.u64 %0, t; }" : "=r"(a) : "l"(p));
    return a;
}
#define CP_ASYNC16(dst, src) \
    asm volatile("cp.async.cg.shared.global [%0], [%1], 16;" \
        :: "r"(dst), "l"(src) : "memory")
#define CP_COMMIT() asm volatile("cp.async.commit_group;" ::: "memory")
#define CP_WAIT2()  asm volatile("cp.async.wait_group 2;" ::: "memory")

#define LDMX4(r0, r1, r2, r3, addr) \
    asm volatile("ldmatrix.sync.aligned.m8n8.x4.shared.b16 {%0,%1,%2,%3}, [%4];" \
        : "=r"(r0), "=r"(r1), "=r"(r2), "=r"(r3) : "r"(addr))
#define LDMX4T(r0, r1, r2, r3, addr) \
    asm volatile("ldmatrix.sync.aligned.m8n8.x4.trans.shared.b16 {%0,%1,%2,%3}, [%4];" \
        : "=r"(r0), "=r"(r1), "=r"(r2), "=r"(r3) : "r"(addr))

__device__ __forceinline__ void mma_f16(float* d, const uint32_t* a, uint32_t b0, uint32_t b1) {
    asm volatile(
        "mma.sync.aligned.m16n8k16.row.col.f32.f16.f16.f32 "
        "{%0,%1,%2,%3}, {%4,%5,%6,%7}, {%8,%9}, {%0,%1,%2,%3};"
        : "+f"(d[0]), "+f"(d[1]), "+f"(d[2]), "+f"(d[3])
        : "r"(a[0]), "r"(a[1]), "r"(a[2]), "r"(a[3]), "r"(b0), "r"(b1));
}

// ---------------------------------------------------------------------------
// fused prep: conv_x | conv_w | bias in one launch (block-range split)
// ---------------------------------------------------------------------------
__global__ void prep_kernel(const float* __restrict__ x,
                            const float* __restrict__ W1,
                            const float* __restrict__ day_emb,
                            const float* __restrict__ b1) {
    int blk = blockIdx.x;
    int tid = threadIdx.x;

    if (blk < XBLKS) {
        // ---- conv_x: fp32 -> fp16 ----
        int i = blk * 256 + tid;
        float4 v = reinterpret_cast<const float4*>(x)[i];
        __half2 h0 = __floats2half2_rn(v.x, v.y);
        __half2 h1 = __floats2half2_rn(v.z, v.w);
        uint2 u;
        u.x = *reinterpret_cast<uint32_t*>(&h0);
        u.y = *reinterpret_cast<uint32_t*>(&h1);
        reinterpret_cast<uint2*>(g_xh)[i] = u;
    } else if (blk < XBLKS + WBLKS) {
        // ---- conv_w: W1[:, :1024, :] fp32 -> fp16 (strided over W1_ROWS) ----
        long long i = (long long)(blk - XBLKS) * 256 + tid;
        long long e = i * 4;
        int p = (int)(e / ((long long)INPUT_DIM * HIDDEN));
        int rem = (int)(e - (long long)p * INPUT_DIM * HIDDEN);
        int k = rem / HIDDEN, n = rem % HIDDEN;
        const float* src = W1 + (size_t)p * W1_ROWS * HIDDEN + (size_t)k * HIDDEN + n;
        float4 v = *reinterpret_cast<const float4*>(src);
        __half2 h0 = __floats2half2_rn(v.x, v.y);
        __half2 h1 = __floats2half2_rn(v.z, v.w);
        uint2 u;
        u.x = *reinterpret_cast<uint32_t*>(&h0);
        u.y = *reinterpret_cast<uint32_t*>(&h1);
        reinterpret_cast<uint2*>(g_W1h)[i] = u;
    } else {
        // ---- bias: c[p][h] = b1 + day_emb @ W1e ----
        int p = blk - XBLKS - WBLKS;
        const float* w = W1 + (size_t)p * W1_ROWS * HIDDEN + (size_t)INPUT_DIM * HIDDEN;
        #pragma unroll
        for (int hh = 0; hh < 2; ++hh) {
            int h = hh * 256 + tid;
            float s = b1[p * HIDDEN + h];
            #pragma unroll
            for (int e = 0; e < DAY_EMB; ++e)
                s += day_emb[p * DAY_EMB + e] * w[e * HIDDEN + h];
            g_bias[p * HIDDEN + h] = s;
        }
    }
}

// ---------------------------------------------------------------------------
// fused fp16 GEMM (x @ W1x[p]) + bias + ReLU + dot(W2[p]) -> partials
//   grid (NT, MT, PRED_LEN); 256 thr = 8 warps (4m x 2n), warp tile 32x64
//   BK=32, 4-stage cp.async (wait_group 2), ONE barrier/iter, 2 CTAs/SM
//   c-loop unrolled 4x so stage indices/addresses are compile-time
// ---------------------------------------------------------------------------
__global__ void __launch_bounds__(THREADS, 2)
mlp_gemm_kernel(const float* __restrict__ W2) {
    extern __shared__ uint4 sm4[];                   // [STAGES][STG_I4]
    __shared__ float cs[BN], ws[BN], red[2][BM];

    const int nt = blockIdx.x, mt = blockIdx.y, p = blockIdx.z;
    const int tid = threadIdx.x, lane = tid & 31, warp = tid >> 5;
    const int wm = warp >> 1, wn = warp & 1;         // 4 x 2
    const int r = lane >> 2, cc = lane & 3;
    const int m0 = mt * BM, n0 = nt * BN;

    const uint32_t smb = smem_u32(sm4);

    // ---- cp.async staging mapping (BK=32) ----
    const int ra = tid >> 2, ca = tid & 3;           // A: rows ra, ra+64; i4 col ca
    const int rb = tid >> 3, cb = tid & 7;           // B: row rb; i4 cols cb, cb+8
    const __half* Agp = g_xh + (size_t)(m0 + ra) * INPUT_DIM + ca * 8;
    const __half* Bgp = g_W1h + ((size_t)p * INPUT_DIM + rb) * HIDDEN + n0 + cb * 8;

    auto issue_stage = [&](int s, int c) {
        const uint32_t st = smb + (uint32_t)(s * STG_I4) * 16;
        const __half* ag = Agp + c * BK;
        CP_ASYNC16(st + (uint32_t)(ra * A_PI4 + ca) * 16, ag);
        CP_ASYNC16(st + (uint32_t)((ra + 64) * A_PI4 + ca) * 16, ag + (size_t)64 * INPUT_DIM);
        const __half* bg = Bgp + (size_t)c * BK * HIDDEN;
        const uint32_t bst = st + (uint32_t)(A_I4 + rb * B_PI4 + cb) * 16;
        CP_ASYNC16(bst, bg);
        CP_ASYNC16(bst + 8 * 16, bg + 64);
    };

    // start the pipeline first
    issue_stage(0, 0); CP_COMMIT();
    issue_stage(1, 1); CP_COMMIT();
    issue_stage(2, 2); CP_COMMIT();

    if (tid < BN) {
        cs[tid] = g_bias[p * HIDDEN + n0 + tid];
        ws[tid] = W2[p * HIDDEN + n0 + tid];
    }

    float acc[2][8][4];
    #pragma unroll
    for (int mi = 0; mi < 2; ++mi)
        #pragma unroll
        for (int ni = 0; ni < 8; ++ni)
            #pragma unroll
            for (int q = 0; q < 4; ++q) acc[mi][ni][q] = 0.0f;

    const int lrow = lane & 15, lhi = lane >> 4;

    #pragma unroll 4
    for (int c = 0; c < KCH; ++c) {
        const int s = c & 3;
        CP_WAIT2();
        __syncthreads();                 // single barrier per iteration

        const uint32_t Ab = smb + (uint32_t)(s * STG_I4) * 16;
        const uint32_t Bb = Ab + (uint32_t)A_I4 * 16;
        #pragma unroll
        for (int kb = 0; kb < 2; ++kb) {
            uint32_t a[2][4], b[4][4];
            #pragma unroll
            for (int mi = 0; mi < 2; ++mi) {
                uint32_t addr = Ab + (uint32_t)((wm * 32 + mi * 16 + lrow) * A_PI4 + kb * 2 + lhi) * 16;
                LDMX4(a[mi][0], a[mi][1], a[mi][2], a[mi][3], addr);
            }
            #pragma unroll
            for (int nj = 0; nj < 4; ++nj) {
                uint32_t addr = Bb + (uint32_t)((kb * 16 + lrow) * B_PI4) * 16
                              + (uint32_t)(wn * 128 + nj * 32 + lhi * 16);
                LDMX4T(b[nj][0], b[nj][1], b[nj][2], b[nj][3], addr);
            }
            // issue next stage AFTER kb=0 fragments are requested
            if (kb == 0) {
                if (c + 3 < KCH) issue_stage((c + 3) & 3, c + 3);
                CP_COMMIT();
            }
            #pragma unroll
            for (int mi = 0; mi < 2; ++mi)
                #pragma unroll
                for (int ni = 0; ni < 8; ++ni) {
                    const uint32_t* bp = b[ni >> 1];
                    uint32_t b0 = (ni & 1) ? bp[2] : bp[0];
                    uint32_t b1 = (ni & 1) ? bp[3] : bp[1];
                    mma_f16(acc[mi][ni], a[mi], b0, b1);
                }
        }
    }

    __syncthreads();

    // ---- fused epilogue: bias + relu + W2 dot, reduce over n ----
    #pragma unroll
    for (int mi = 0; mi < 2; ++mi) {
        float rs0 = 0.0f, rs1 = 0.0f;
        #pragma unroll
        for (int ni = 0; ni < 8; ++ni) {
            int col = wn * 64 + ni * 8 + cc * 2;
            float h0 = acc[mi][ni][0] + cs[col];
            float h1 = acc[mi][ni][1] + cs[col + 1];
            float h2 = acc[mi][ni][2] + cs[col];
            float h3 = acc[mi][ni][3] + cs[col + 1];
            rs0 += fmaxf(h0, 0.0f) * ws[col] + fmaxf(h1, 0.0f) * ws[col + 1];
            rs1 += fmaxf(h2, 0.0f) * ws[col] + fmaxf(h3, 0.0f) * ws[col + 1];
        }
        #pragma unroll
        for (int off = 1; off < 4; off <<= 1) {
            rs0 += __shfl_xor_sync(0xffffffffu, rs0, off);
            rs1 += __shfl_xor_sync(0xffffffffu, rs1, off);
        }
        if ((lane & 3) == 0) {
            int row = wm * 32 + mi * 16 + r;
            red[wn][row]     = rs0;
            red[wn][row + 8] = rs1;
        }
    }
    __syncthreads();

    if (tid < BM) {
        float v = red[0][tid] + red[1][tid];
        g_part[((size_t)nt * BATCH + m0 + tid) * PRED_LEN + p] = v;
    }
}

// ---------------------------------------------------------------------------
__global__ void reduce_kernel(const float* __restrict__ b2, float* __restrict__ out) {
    int idx = blockIdx.x * blockDim.x + threadIdx.x;
    if (idx >= BATCH * PRED_LEN) return;
    int p = idx % PRED_LEN;
    float s = b2[p];
    #pragma unroll
    for (int nt = 0; nt < NT; ++nt)
        s += g_part[(size_t)nt * BATCH * PRED_LEN + idx];
    out[idx] = s;
}

// ---------------------------------------------------------------------------
extern "C" void kernel_launch(void* const* d_in, const int* in_sizes, int n_in,
                              void* d_out, int out_size) {
    const float* x       = (const float*)d_in[0];
    const float* day_emb = (const float*)d_in[1];
    const float* W1      = (const float*)d_in[2];
    const float* b1      = (const float*)d_in[3];
    const float* W2      = (const float*)d_in[4];
    const float* b2      = (const float*)d_in[5];
    float* out = (float*)d_out;

    const int SMEM = STAGES * STG_I4 * 16;   // 75776 bytes
    cudaFuncSetAttribute(mlp_gemm_kernel,
                         cudaFuncAttributeMaxDynamicSharedMemorySize, SMEM);

    prep_kernel<<<PREP_BLKS, 256>>>(x, W1, day_emb, b1);

    dim3 grid(NT, MT, PRED_LEN);
    mlp_gemm_kernel<<<grid, THREADS, SMEM>>>(W2);

    int total = BATCH * PRED_LEN;
    reduce_kernel<<<(total + 255) / 256, 256>>>(b2, out);
}

// round 14
// speedup vs baseline: 1.3025x; 1.0253x over previous
#include <cuda_runtime.h>
#include <cuda_fp16.h>
#include <cstdint>

#define INPUT_DIM 1024
#define DAY_EMB   8
#define PRED_LEN  96
#define HIDDEN    512
#define BATCH     4096
#define W1_ROWS   (INPUT_DIM + DAY_EMB)

#define BM 128
#define BN 128
#define BK 32
#define KCH (INPUT_DIM / BK)     // 32
#define NT (HIDDEN / BN)         // 4
#define MT (BATCH / BM)          // 32
#define THREADS 256
#define STAGES 4

// smem per stage (uint4 units): A = 128 rows * 5 (4 data + 1 pad)
//                               B = 32 rows * 17 (16 data + 1 pad)
#define A_PI4  5
#define B_PI4  17
#define A_I4   (BM * A_PI4)          // 640
#define B_I4   (BK * B_PI4)          // 544
#define STG_I4 (A_I4 + B_I4)         // 1184 (18944 B/stage)

// fused prep launch geometry
#define XBLKS (BATCH * INPUT_DIM / 4 / 256)                       // 4096
#define WBLKS ((int)((long long)PRED_LEN * INPUT_DIM * HIDDEN / 4 / 256))  // 49152
#define PREP_BLKS (XBLKS + WBLKS + PRED_LEN)

// ---------------- scratch ----------------------------------------------------
__device__ __half g_xh[(size_t)BATCH * INPUT_DIM];
__device__ __half g_W1h[(size_t)PRED_LEN * INPUT_DIM * HIDDEN];
__device__ float  g_bias[PRED_LEN * HIDDEN];
__device__ float  g_part[NT * BATCH * PRED_LEN];

// ---------------- helpers ----------------------------------------------------
__device__ __forceinline__ uint32_t smem_u32(const void* p) {
    uint32_t a;
    asm("{ .reg .u64 t; cvta.to.shared.u64 t, %1; cvt.u32.u64 %0, t; }" : "=r"(a) : "l"(p));
    return a;
}
#define CP_ASYNC16(dst, src) \
    asm volatile("cp.async.cg.shared.global [%0], [%1], 16;" \
        :: "r"(dst), "l"(src) : "memory")
#define CP_COMMIT() asm volatile("cp.async.commit_group;" ::: "memory")
#define CP_WAIT2()  asm volatile("cp.async.wait_group 2;" ::: "memory")

#define LDMX4(r0, r1, r2, r3, addr) \
    asm volatile("ldmatrix.sync.aligned.m8n8.x4.shared.b16 {%0,%1,%2,%3}, [%4];" \
        : "=r"(r0), "=r"(r1), "=r"(r2), "=r"(r3) : "r"(addr))
#define LDMX4T(r0, r1, r2, r3, addr) \
    asm volatile("ldmatrix.sync.aligned.m8n8.x4.trans.shared.b16 {%0,%1,%2,%3}, [%4];" \
        : "=r"(r0), "=r"(r1), "=r"(r2), "=r"(r3) : "r"(addr))

__device__ __forceinline__ void mma_f16(float* d, const uint32_t* a, uint32_t b0, uint32_t b1) {
    asm volatile(
        "mma.sync.aligned.m16n8k16.row.col.f32.f16.f16.f32 "
        "{%0,%1,%2,%3}, {%4,%5,%6,%7}, {%8,%9}, {%0,%1,%2,%3};"
        : "+f"(d[0]), "+f"(d[1]), "+f"(d[2]), "+f"(d[3])
        : "r"(a[0]), "r"(a[1]), "r"(a[2]), "r"(a[3]), "r"(b0), "r"(b1));
}

// streaming global ld/st (evict-first) to keep x L2-resident
__device__ __forceinline__ float4 ldg_cs_f4(const float* p) {
    float4 v;
    asm volatile("ld.global.cs.v4.f32 {%0,%1,%2,%3}, [%4];"
        : "=f"(v.x), "=f"(v.y), "=f"(v.z), "=f"(v.w) : "l"(p));
    return v;
}
__device__ __forceinline__ void stg_cs_u2(void* p, uint2 v) {
    asm volatile("st.global.cs.v2.u32 [%0], {%1,%2};" :: "l"(p), "r"(v.x), "r"(v.y));
}

// ---------------------------------------------------------------------------
// fused prep: conv_x | conv_w | bias in one launch (block-range split)
// ---------------------------------------------------------------------------
__global__ void prep_kernel(const float* __restrict__ x,
                            const float* __restrict__ W1,
                            const float* __restrict__ day_emb,
                            const float* __restrict__ b1) {
    int blk = blockIdx.x;
    int tid = threadIdx.x;

    if (blk < XBLKS) {
        // ---- conv_x: fp32 -> fp16 (x result kept cacheable: gemm re-reads) --
        int i = blk * 256 + tid;
        float4 v = reinterpret_cast<const float4*>(x)[i];
        __half2 h0 = __floats2half2_rn(v.x, v.y);
        __half2 h1 = __floats2half2_rn(v.z, v.w);
        uint2 u;
        u.x = *reinterpret_cast<uint32_t*>(&h0);
        u.y = *reinterpret_cast<uint32_t*>(&h1);
        reinterpret_cast<uint2*>(g_xh)[i] = u;
    } else if (blk < XBLKS + WBLKS) {
        // ---- conv_w: streaming in AND out (no reuse; don't pollute L2) ----
        long long i = (long long)(blk - XBLKS) * 256 + tid;
        long long e = i * 4;
        int p = (int)(e / ((long long)INPUT_DIM * HIDDEN));
        int rem = (int)(e - (long long)p * INPUT_DIM * HIDDEN);
        int k = rem / HIDDEN, n = rem % HIDDEN;
        const float* src = W1 + (size_t)p * W1_ROWS * HIDDEN + (size_t)k * HIDDEN + n;
        float4 v = ldg_cs_f4(src);
        __half2 h0 = __floats2half2_rn(v.x, v.y);
        __half2 h1 = __floats2half2_rn(v.z, v.w);
        uint2 u;
        u.x = *reinterpret_cast<uint32_t*>(&h0);
        u.y = *reinterpret_cast<uint32_t*>(&h1);
        stg_cs_u2(reinterpret_cast<uint2*>(g_W1h) + i, u);
    } else {
        // ---- bias: c[p][h] = b1 + day_emb @ W1e ----
        int p = blk - XBLKS - WBLKS;
        const float* w = W1 + (size_t)p * W1_ROWS * HIDDEN + (size_t)INPUT_DIM * HIDDEN;
        #pragma unroll
        for (int hh = 0; hh < 2; ++hh) {
            int h = hh * 256 + tid;
            float s = b1[p * HIDDEN + h];
            #pragma unroll
            for (int e = 0; e < DAY_EMB; ++e)
                s += day_emb[p * DAY_EMB + e] * w[e * HIDDEN + h];
            g_bias[p * HIDDEN + h] = s;
        }
    }
}

// ---------------------------------------------------------------------------
// fused fp16 GEMM (x @ W1x[p]) + bias + ReLU + dot(W2[p]) -> partials
//   grid (NT, MT, PRED_LEN); 256 thr = 8 warps (4m x 2n), warp tile 32x64
//   BK=32, 4-stage cp.async (wait_group 2), ONE barrier/iter, 2 CTAs/SM
//   c-loop unrolled 4x; staging split A@kb0 / B@kb1 to spread LSU pressure
// ---------------------------------------------------------------------------
__global__ void __launch_bounds__(THREADS, 2)
mlp_gemm_kernel(const float* __restrict__ W2) {
    extern __shared__ uint4 sm4[];                   // [STAGES][STG_I4]
    __shared__ float cs[BN], ws[BN], red[2][BM];

    const int nt = blockIdx.x, mt = blockIdx.y, p = blockIdx.z;
    const int tid = threadIdx.x, lane = tid & 31, warp = tid >> 5;
    const int wm = warp >> 1, wn = warp & 1;         // 4 x 2
    const int r = lane >> 2, cc = lane & 3;
    const int m0 = mt * BM, n0 = nt * BN;

    const uint32_t smb = smem_u32(sm4);

    // ---- cp.async staging mapping (BK=32) ----
    const int ra = tid >> 2, ca = tid & 3;           // A: rows ra, ra+64; i4 col ca
    const int rb = tid >> 3, cb = tid & 7;           // B: row rb; i4 cols cb, cb+8
    const __half* Agp = g_xh + (size_t)(m0 + ra) * INPUT_DIM + ca * 8;
    const __half* Bgp = g_W1h + ((size_t)p * INPUT_DIM + rb) * HIDDEN + n0 + cb * 8;

    auto issue_A = [&](int s, int c) {
        const uint32_t st = smb + (uint32_t)(s * STG_I4) * 16;
        const __half* ag = Agp + c * BK;
        CP_ASYNC16(st + (uint32_t)(ra * A_PI4 + ca) * 16, ag);
        CP_ASYNC16(st + (uint32_t)((ra + 64) * A_PI4 + ca) * 16, ag + (size_t)64 * INPUT_DIM);
    };
    auto issue_B = [&](int s, int c) {
        const uint32_t st = smb + (uint32_t)(s * STG_I4) * 16;
        const __half* bg = Bgp + (size_t)c * BK * HIDDEN;
        const uint32_t bst = st + (uint32_t)(A_I4 + rb * B_PI4 + cb) * 16;
        CP_ASYNC16(bst, bg);
        CP_ASYNC16(bst + 8 * 16, bg + 64);
    };

    // start the pipeline first
    issue_A(0, 0); issue_B(0, 0); CP_COMMIT();
    issue_A(1, 1); issue_B(1, 1); CP_COMMIT();
    issue_A(2, 2); issue_B(2, 2); CP_COMMIT();

    if (tid < BN) {
        cs[tid] = g_bias[p * HIDDEN + n0 + tid];
        ws[tid] = W2[p * HIDDEN + n0 + tid];
    }

    float acc[2][8][4];
    #pragma unroll
    for (int mi = 0; mi < 2; ++mi)
        #pragma unroll
        for (int ni = 0; ni < 8; ++ni)
            #pragma unroll
            for (int q = 0; q < 4; ++q) acc[mi][ni][q] = 0.0f;

    const int lrow = lane & 15, lhi = lane >> 4;

    #pragma unroll 4
    for (int c = 0; c < KCH; ++c) {
        const int s = c & 3;
        CP_WAIT2();
        __syncthreads();                 // single barrier per iteration

        const uint32_t Ab = smb + (uint32_t)(s * STG_I4) * 16;
        const uint32_t Bb = Ab + (uint32_t)A_I4 * 16;
        #pragma unroll
        for (int kb = 0; kb < 2; ++kb) {
            uint32_t a[2][4], b[4][4];
            #pragma unroll
            for (int mi = 0; mi < 2; ++mi) {
                uint32_t addr = Ab + (uint32_t)((wm * 32 + mi * 16 + lrow) * A_PI4 + kb * 2 + lhi) * 16;
                LDMX4(a[mi][0], a[mi][1], a[mi][2], a[mi][3], addr);
            }
            #pragma unroll
            for (int nj = 0; nj < 4; ++nj) {
                uint32_t addr = Bb + (uint32_t)((kb * 16 + lrow) * B_PI4) * 16
                              + (uint32_t)(wn * 128 + nj * 32 + lhi * 16);
                LDMX4T(b[nj][0], b[nj][1], b[nj][2], b[nj][3], addr);
            }
            // spread staging: A at kb=0, B + commit at kb=1, after fragment
            // loads so the ldmatrix->mma critical path starts immediately
            if (kb == 0) {
                if (c + 3 < KCH) issue_A((c + 3) & 3, c + 3);
            } else {
                if (c + 3 < KCH) issue_B((c + 3) & 3, c + 3);
                CP_COMMIT();
            }
            #pragma unroll
            for (int mi = 0; mi < 2; ++mi)
                #pragma unroll
                for (int ni = 0; ni < 8; ++ni) {
                    const uint32_t* bp = b[ni >> 1];
                    uint32_t b0 = (ni & 1) ? bp[2] : bp[0];
                    uint32_t b1 = (ni & 1) ? bp[3] : bp[1];
                    mma_f16(acc[mi][ni], a[mi], b0, b1);
                }
        }
    }

    __syncthreads();

    // ---- fused epilogue: bias + relu + W2 dot, reduce over n ----
    #pragma unroll
    for (int mi = 0; mi < 2; ++mi) {
        float rs0 = 0.0f, rs1 = 0.0f;
        #pragma unroll
        for (int ni = 0; ni < 8; ++ni) {
            int col = wn * 64 + ni * 8 + cc * 2;
            float h0 = acc[mi][ni][0] + cs[col];
            float h1 = acc[mi][ni][1] + cs[col + 1];
            float h2 = acc[mi][ni][2] + cs[col];
            float h3 = acc[mi][ni][3] + cs[col + 1];
            rs0 += fmaxf(h0, 0.0f) * ws[col] + fmaxf(h1, 0.0f) * ws[col + 1];
            rs1 += fmaxf(h2, 0.0f) * ws[col] + fmaxf(h3, 0.0f) * ws[col + 1];
        }
        #pragma unroll
        for (int off = 1; off < 4; off <<= 1) {
            rs0 += __shfl_xor_sync(0xffffffffu, rs0, off);
            rs1 += __shfl_xor_sync(0xffffffffu, rs1, off);
        }
        if ((lane & 3) == 0) {
            int row = wm * 32 + mi * 16 + r;
            red[wn][row]     = rs0;
            red[wn][row + 8] = rs1;
        }
    }
    __syncthreads();

    if (tid < BM) {
        float v = red[0][tid] + red[1][tid];
        g_part[((size_t)nt * BATCH + m0 + tid) * PRED_LEN + p] = v;
    }
}

// ---------------------------------------------------------------------------
__global__ void reduce_kernel(const float* __restrict__ b2, float* __restrict__ out) {
    int idx = blockIdx.x * blockDim.x + threadIdx.x;
    if (idx >= BATCH * PRED_LEN) return;
    int p = idx % PRED_LEN;
    float s = b2[p];
    #pragma unroll
    for (int nt = 0; nt < NT; ++nt)
        s += g_part[(size_t)nt * BATCH * PRED_LEN + idx];
    out[idx] = s;
}

// ---------------------------------------------------------------------------
extern "C" void kernel_launch(void* const* d_in, const int* in_sizes, int n_in,
                              void* d_out, int out_size) {
    const float* x       = (const float*)d_in[0];
    const float* day_emb = (const float*)d_in[1];
    const float* W1      = (const float*)d_in[2];
    const float* b1      = (const float*)d_in[3];
    const float* W2      = (const float*)d_in[4];
    const float* b2      = (const float*)d_in[5];
    float* out = (float*)d_out;

    const int SMEM = STAGES * STG_I4 * 16;   // 75776 bytes
    cudaFuncSetAttribute(mlp_gemm_kernel,
                         cudaFuncAttributeMaxDynamicSharedMemorySize, SMEM);

    prep_kernel<<<PREP_BLKS, 256>>>(x, W1, day_emb, b1);

    dim3 grid(NT, MT, PRED_LEN);
    mlp_gemm_kernel<<<grid, THREADS, SMEM>>>(W2);

    int total = BATCH * PRED_LEN;
    reduce_kernel<<<(total + 255) / 256, 256>>>(b2, out);
}

// round 15
// speedup vs baseline: 1.3092x; 1.0051x over previous
#include <cuda_runtime.h>
#include <cuda_fp16.h>
#include <cstdint>

#define INPUT_DIM 1024
#define DAY_EMB   8
#define PRED_LEN  96
#define HIDDEN    512
#define BATCH     4096
#define W1_ROWS   (INPUT_DIM + DAY_EMB)

#define BM 128
#define BN 128
#define BK 32
#define KCH (INPUT_DIM / BK)     // 32
#define NT (HIDDEN / BN)         // 4
#define MT (BATCH / BM)          // 32
#define THREADS 256
#define STAGES 4

// smem per stage (uint4 units): A = 128 rows * 5 (4 data + 1 pad)
//                               B = 32 rows * 17 (16 data + 1 pad)
#define A_PI4  5
#define B_PI4  17
#define A_I4   (BM * A_PI4)          // 640
#define B_I4   (BK * B_PI4)          // 544
#define STG_I4 (A_I4 + B_I4)         // 1184 (18944 B/stage)

// fused prep launch geometry (conv_w: 2 float4 per thread)
#define XBLKS (BATCH * INPUT_DIM / 4 / 256)                                // 4096
#define WBLKS ((int)((long long)PRED_LEN * INPUT_DIM * HIDDEN / 8 / 256))  // 24576
#define PREP_BLKS (XBLKS + WBLKS + PRED_LEN)

// ---------------- scratch ----------------------------------------------------
__device__ __half g_xh[(size_t)BATCH * INPUT_DIM];
__device__ __half g_W1h[(size_t)PRED_LEN * INPUT_DIM * HIDDEN];
__device__ float  g_bias[PRED_LEN * HIDDEN];
__device__ float  g_part[NT * BATCH * PRED_LEN];

// ---------------- helpers ----------------------------------------------------
__device__ __forceinline__ uint32_t smem_u32(const void* p) {
    uint32_t a;
    asm("{ .reg .u64 t; cvta.to.shared.u64 t, %1; cvt.u32.u64 %0, t; }" : "=r"(a) : "l"(p));
    return a;
}
#define CP_ASYNC16(dst, src) \
    asm volatile("cp.async.cg.shared.global [%0], [%1], 16;" \
        :: "r"(dst), "l"(src) : "memory")
#define CP_COMMIT() asm volatile("cp.async.commit_group;" ::: "memory")
#define CP_WAIT2()  asm volatile("cp.async.wait_group 2;" ::: "memory")

#define LDMX4(r0, r1, r2, r3, addr) \
    asm volatile("ldmatrix.sync.aligned.m8n8.x4.shared.b16 {%0,%1,%2,%3}, [%4];" \
        : "=r"(r0), "=r"(r1), "=r"(r2), "=r"(r3) : "r"(addr))
#define LDMX4T(r0, r1, r2, r3, addr) \
    asm volatile("ldmatrix.sync.aligned.m8n8.x4.trans.shared.b16 {%0,%1,%2,%3}, [%4];" \
        : "=r"(r0), "=r"(r1), "=r"(r2), "=r"(r3) : "r"(addr))

__device__ __forceinline__ void mma_f16(float* d, const uint32_t* a, uint32_t b0, uint32_t b1) {
    asm volatile(
        "mma.sync.aligned.m16n8k16.row.col.f32.f16.f16.f32 "
        "{%0,%1,%2,%3}, {%4,%5,%6,%7}, {%8,%9}, {%0,%1,%2,%3};"
        : "+f"(d[0]), "+f"(d[1]), "+f"(d[2]), "+f"(d[3])
        : "r"(a[0]), "r"(a[1]), "r"(a[2]), "r"(a[3]), "r"(b0), "r"(b1));
}

// streaming global ld/st (evict-first) to keep x L2-resident
__device__ __forceinline__ float4 ldg_cs_f4(const float* p) {
    float4 v;
    asm volatile("ld.global.cs.v4.f32 {%0,%1,%2,%3}, [%4];"
        : "=f"(v.x), "=f"(v.y), "=f"(v.z), "=f"(v.w) : "l"(p));
    return v;
}
__device__ __forceinline__ void stg_cs_u2(void* p, uint2 v) {
    asm volatile("st.global.cs.v2.u32 [%0], {%1,%2};" :: "l"(p), "r"(v.x), "r"(v.y));
}

__device__ __forceinline__ uint2 cvt_f4_h4(float4 v) {
    __half2 h0 = __floats2half2_rn(v.x, v.y);
    __half2 h1 = __floats2half2_rn(v.z, v.w);
    uint2 u;
    u.x = *reinterpret_cast<uint32_t*>(&h0);
    u.y = *reinterpret_cast<uint32_t*>(&h1);
    return u;
}

// ---------------------------------------------------------------------------
// fused prep: conv_x | conv_w | bias in one launch (block-range split)
// ---------------------------------------------------------------------------
__global__ void prep_kernel(const float* __restrict__ x,
                            const float* __restrict__ W1,
                            const float* __restrict__ day_emb,
                            const float* __restrict__ b1) {
    int blk = blockIdx.x;
    int tid = threadIdx.x;

    if (blk < XBLKS) {
        // ---- conv_x: fp32 -> fp16 (kept cacheable: gemm re-reads x) ----
        int i = blk * 256 + tid;
        float4 v = reinterpret_cast<const float4*>(x)[i];
        reinterpret_cast<uint2*>(g_xh)[i] = cvt_f4_h4(v);
    } else if (blk < XBLKS + WBLKS) {
        // ---- conv_w: 2 float4/thread; W1[p] rows 0..1023 are CONTIGUOUS,
        //      so only one divide by (INPUT_DIM*HIDDEN) is needed ----
        long long i0 = ((long long)(blk - XBLKS) * 256 + tid) * 2;   // float4 idx
        long long e = i0 * 4;                                        // float idx
        int p = (int)(e / ((long long)INPUT_DIM * HIDDEN));
        long long rem = e - (long long)p * INPUT_DIM * HIDDEN;
        const float* src = W1 + (size_t)p * W1_ROWS * HIDDEN + rem;
        float4 v0 = ldg_cs_f4(src);
        float4 v1 = ldg_cs_f4(src + 4);
        stg_cs_u2(reinterpret_cast<uint2*>(g_W1h) + i0,     cvt_f4_h4(v0));
        stg_cs_u2(reinterpret_cast<uint2*>(g_W1h) + i0 + 1, cvt_f4_h4(v1));
    } else {
        // ---- bias: c[p][h] = b1 + day_emb @ W1e ----
        int p = blk - XBLKS - WBLKS;
        const float* w = W1 + (size_t)p * W1_ROWS * HIDDEN + (size_t)INPUT_DIM * HIDDEN;
        #pragma unroll
        for (int hh = 0; hh < 2; ++hh) {
            int h = hh * 256 + tid;
            float s = b1[p * HIDDEN + h];
            #pragma unroll
            for (int e = 0; e < DAY_EMB; ++e)
                s += day_emb[p * DAY_EMB + e] * w[e * HIDDEN + h];
            g_bias[p * HIDDEN + h] = s;
        }
    }
}

// ---------------------------------------------------------------------------
// fused fp16 GEMM (x @ W1x[p]) + bias + ReLU + dot(W2[p]) -> partials
//   grid (NT, MT, PRED_LEN); 256 thr = 8 warps (4m x 2n), warp tile 32x64
//   BK=32, 4-stage cp.async (wait_group 2), ONE barrier/iter, 2 CTAs/SM
//   c-loop unrolled 4x; staging split A@kb0 / B@kb1
// ---------------------------------------------------------------------------
__global__ void __launch_bounds__(THREADS, 2)
mlp_gemm_kernel(const float* __restrict__ W2) {
    extern __shared__ uint4 sm4[];                   // [STAGES][STG_I4]
    __shared__ float cs[BN], ws[BN], red[2][BM];

    const int nt = blockIdx.x, mt = blockIdx.y, p = blockIdx.z;
    const int tid = threadIdx.x, lane = tid & 31, warp = tid >> 5;
    const int wm = warp >> 1, wn = warp & 1;         // 4 x 2
    const int r = lane >> 2, cc = lane & 3;
    const int m0 = mt * BM, n0 = nt * BN;

    const uint32_t smb = smem_u32(sm4);

    // ---- cp.async staging mapping (BK=32) ----
    const int ra = tid >> 2, ca = tid & 3;           // A: rows ra, ra+64; i4 col ca
    const int rb = tid >> 3, cb = tid & 7;           // B: row rb; i4 cols cb, cb+8
    const __half* Agp = g_xh + (size_t)(m0 + ra) * INPUT_DIM + ca * 8;
    const __half* Bgp = g_W1h + ((size_t)p * INPUT_DIM + rb) * HIDDEN + n0 + cb * 8;

    auto issue_A = [&](int s, int c) {
        const uint32_t st = smb + (uint32_t)(s * STG_I4) * 16;
        const __half* ag = Agp + c * BK;
        CP_ASYNC16(st + (uint32_t)(ra * A_PI4 + ca) * 16, ag);
        CP_ASYNC16(st + (uint32_t)((ra + 64) * A_PI4 + ca) * 16, ag + (size_t)64 * INPUT_DIM);
    };
    auto issue_B = [&](int s, int c) {
        const uint32_t st = smb + (uint32_t)(s * STG_I4) * 16;
        const __half* bg = Bgp + (size_t)c * BK * HIDDEN;
        const uint32_t bst = st + (uint32_t)(A_I4 + rb * B_PI4 + cb) * 16;
        CP_ASYNC16(bst, bg);
        CP_ASYNC16(bst + 8 * 16, bg + 64);
    };

    // start the pipeline first
    issue_A(0, 0); issue_B(0, 0); CP_COMMIT();
    issue_A(1, 1); issue_B(1, 1); CP_COMMIT();
    issue_A(2, 2); issue_B(2, 2); CP_COMMIT();

    if (tid < BN) {
        cs[tid] = g_bias[p * HIDDEN + n0 + tid];
        ws[tid] = W2[p * HIDDEN + n0 + tid];
    }

    float acc[2][8][4];
    #pragma unroll
    for (int mi = 0; mi < 2; ++mi)
        #pragma unroll
        for (int ni = 0; ni < 8; ++ni)
            #pragma unroll
            for (int q = 0; q < 4; ++q) acc[mi][ni][q] = 0.0f;

    const int lrow = lane & 15, lhi = lane >> 4;

    #pragma unroll 4
    for (int c = 0; c < KCH; ++c) {
        const int s = c & 3;
        CP_WAIT2();
        __syncthreads();                 // single barrier per iteration

        const uint32_t Ab = smb + (uint32_t)(s * STG_I4) * 16;
        const uint32_t Bb = Ab + (uint32_t)A_I4 * 16;
        #pragma unroll
        for (int kb = 0; kb < 2; ++kb) {
            uint32_t a[2][4], b[4][4];
            #pragma unroll
            for (int mi = 0; mi < 2; ++mi) {
                uint32_t addr = Ab + (uint32_t)((wm * 32 + mi * 16 + lrow) * A_PI4 + kb * 2 + lhi) * 16;
                LDMX4(a[mi][0], a[mi][1], a[mi][2], a[mi][3], addr);
            }
            #pragma unroll
            for (int nj = 0; nj < 4; ++nj) {
                uint32_t addr = Bb + (uint32_t)((kb * 16 + lrow) * B_PI4) * 16
                              + (uint32_t)(wn * 128 + nj * 32 + lhi * 16);
                LDMX4T(b[nj][0], b[nj][1], b[nj][2], b[nj][3], addr);
            }
            // spread staging: A at kb=0, B + commit at kb=1
            if (kb == 0) {
                if (c + 3 < KCH) issue_A((c + 3) & 3, c + 3);
            } else {
                if (c + 3 < KCH) issue_B((c + 3) & 3, c + 3);
                CP_COMMIT();
            }
            #pragma unroll
            for (int mi = 0; mi < 2; ++mi)
                #pragma unroll
                for (int ni = 0; ni < 8; ++ni) {
                    const uint32_t* bp = b[ni >> 1];
                    uint32_t b0 = (ni & 1) ? bp[2] : bp[0];
                    uint32_t b1 = (ni & 1) ? bp[3] : bp[1];
                    mma_f16(acc[mi][ni], a[mi], b0, b1);
                }
        }
    }

    __syncthreads();

    // ---- fused epilogue: bias + relu + W2 dot, reduce over n ----
    #pragma unroll
    for (int mi = 0; mi < 2; ++mi) {
        float rs0 = 0.0f, rs1 = 0.0f;
        #pragma unroll
        for (int ni = 0; ni < 8; ++ni) {
            int col = wn * 64 + ni * 8 + cc * 2;
            float h0 = acc[mi][ni][0] + cs[col];
            float h1 = acc[mi][ni][1] + cs[col + 1];
            float h2 = acc[mi][ni][2] + cs[col];
            float h3 = acc[mi][ni][3] + cs[col + 1];
            rs0 += fmaxf(h0, 0.0f) * ws[col] + fmaxf(h1, 0.0f) * ws[col + 1];
            rs1 += fmaxf(h2, 0.0f) * ws[col] + fmaxf(h3, 0.0f) * ws[col + 1];
        }
        #pragma unroll
        for (int off = 1; off < 4; off <<= 1) {
            rs0 += __shfl_xor_sync(0xffffffffu, rs0, off);
            rs1 += __shfl_xor_sync(0xffffffffu, rs1, off);
        }
        if ((lane & 3) == 0) {
            int row = wm * 32 + mi * 16 + r;
            red[wn][row]     = rs0;
            red[wn][row + 8] = rs1;
        }
    }
    __syncthreads();

    if (tid < BM) {
        float v = red[0][tid] + red[1][tid];
        g_part[((size_t)nt * BATCH + m0 + tid) * PRED_LEN + p] = v;
    }
}

// ---------------------------------------------------------------------------
// reduce partials + b2 -> out[b][p]   (float4; 4-aligned idx never wraps p)
// ---------------------------------------------------------------------------
__global__ void reduce_kernel(const float* __restrict__ b2, float* __restrict__ out) {
    int i4 = blockIdx.x * blockDim.x + threadIdx.x;
    if (i4 >= BATCH * PRED_LEN / 4) return;
    int idx = i4 * 4;
    int p0 = idx % PRED_LEN;
    float4 s;
    s.x = b2[p0];
    s.y = b2[p0 + 1];
    s.z = b2[p0 + 2];
    s.w = b2[p0 + 3];
    #pragma unroll
    for (int nt = 0; nt < NT; ++nt) {
        float4 v = *reinterpret_cast<const float4*>(
            g_part + (size_t)nt * BATCH * PRED_LEN + idx);
        s.x += v.x; s.y += v.y; s.z += v.z; s.w += v.w;
    }
    *reinterpret_cast<float4*>(out + idx) = s;
}

// ---------------------------------------------------------------------------
extern "C" void kernel_launch(void* const* d_in, const int* in_sizes, int n_in,
                              void* d_out, int out_size) {
    const float* x       = (const float*)d_in[0];
    const float* day_emb = (const float*)d_in[1];
    const float* W1      = (const float*)d_in[2];
    const float* b1      = (const float*)d_in[3];
    const float* W2      = (const float*)d_in[4];
    const float* b2      = (const float*)d_in[5];
    float* out = (float*)d_out;

    const int SMEM = STAGES * STG_I4 * 16;   // 75776 bytes
    cudaFuncSetAttribute(mlp_gemm_kernel,
                         cudaFuncAttributeMaxDynamicSharedMemorySize, SMEM);

    prep_kernel<<<PREP_BLKS, 256>>>(x, W1, day_emb, b1);

    dim3 grid(NT, MT, PRED_LEN);
    mlp_gemm_kernel<<<grid, THREADS, SMEM>>>(W2);

    int total4 = BATCH * PRED_LEN / 4;
    reduce_kernel<<<(total4 + 255) / 256, 256>>>(b2, out);
}

// round 16
// speedup vs baseline: 1.3598x; 1.0387x over previous
#include <cuda_runtime.h>
#include <cuda_fp16.h>
#include <cstdint>

#define INPUT_DIM 1024
#define DAY_EMB   8
#define PRED_LEN  96
#define HIDDEN    512
#define BATCH     4096
#define W1_ROWS   (INPUT_DIM + DAY_EMB)

#define BM 128
#define BN 128
#define BK 32
#define KCH (INPUT_DIM / BK)     // 32
#define NT (HIDDEN / BN)         // 4
#define MT (BATCH / BM)          // 32
#define THREADS 256
#define STAGES 4

// smem per stage (uint4 units): A = 128 rows * 5 (4 data + 1 pad)
//                               B = 32 rows * 17 (16 data + 1 pad)
#define A_PI4  5
#define B_PI4  17
#define A_I4   (BM * A_PI4)          // 640
#define B_I4   (BK * B_PI4)          // 544
#define STG_I4 (A_I4 + B_I4)         // 1184 (18944 B/stage)

// fused prep launch geometry (conv_w: 2 float4 per thread)
#define XBLKS (BATCH * INPUT_DIM / 4 / 256)                                // 4096
#define WBLKS ((int)((long long)PRED_LEN * INPUT_DIM * HIDDEN / 8 / 256))  // 24576
#define PREP_BLKS (XBLKS + WBLKS + PRED_LEN)

// ---------------- scratch ----------------------------------------------------
__device__ __half g_xh[(size_t)BATCH * INPUT_DIM];
__device__ __half g_W1h[(size_t)PRED_LEN * INPUT_DIM * HIDDEN];
__device__ float  g_bias[PRED_LEN * HIDDEN];
__device__ float  g_part[NT * PRED_LEN * BATCH];   // [nt][p][b]  (coalesced)

// ---------------- helpers ----------------------------------------------------
__device__ __forceinline__ uint32_t smem_u32(const void* p) {
    uint32_t a;
    asm("{ .reg .u64 t; cvta.to.shared.u64 t, %1; cvt.u32.u64 %0, t; }" : "=r"(a) : "l"(p));
    return a;
}
#define CP_ASYNC16(dst, src) \
    asm volatile("cp.async.cg.shared.global [%0], [%1], 16;" \
        :: "r"(dst), "l"(src) : "memory")
#define CP_COMMIT() asm volatile("cp.async.commit_group;" ::: "memory")
#define CP_WAIT2()  asm volatile("cp.async.wait_group 2;" ::: "memory")

#define LDMX4(r0, r1, r2, r3, addr) \
    asm volatile("ldmatrix.sync.aligned.m8n8.x4.shared.b16 {%0,%1,%2,%3}, [%4];" \
        : "=r"(r0), "=r"(r1), "=r"(r2), "=r"(r3) : "r"(addr))
#define LDMX4T(r0, r1, r2, r3, addr) \
    asm volatile("ldmatrix.sync.aligned.m8n8.x4.trans.shared.b16 {%0,%1,%2,%3}, [%4];" \
        : "=r"(r0), "=r"(r1), "=r"(r2), "=r"(r3) : "r"(addr))

__device__ __forceinline__ void mma_f16(float* d, const uint32_t* a, uint32_t b0, uint32_t b1) {
    asm volatile(
        "mma.sync.aligned.m16n8k16.row.col.f32.f16.f16.f32 "
        "{%0,%1,%2,%3}, {%4,%5,%6,%7}, {%8,%9}, {%0,%1,%2,%3};"
        : "+f"(d[0]), "+f"(d[1]), "+f"(d[2]), "+f"(d[3])
        : "r"(a[0]), "r"(a[1]), "r"(a[2]), "r"(a[3]), "r"(b0), "r"(b1));
}

// streaming global ld/st (evict-first) to keep x L2-resident
__device__ __forceinline__ float4 ldg_cs_f4(const float* p) {
    float4 v;
    asm volatile("ld.global.cs.v4.f32 {%0,%1,%2,%3}, [%4];"
        : "=f"(v.x), "=f"(v.y), "=f"(v.z), "=f"(v.w) : "l"(p));
    return v;
}
__device__ __forceinline__ void stg_cs_u2(void* p, uint2 v) {
    asm volatile("st.global.cs.v2.u32 [%0], {%1,%2};" :: "l"(p), "r"(v.x), "r"(v.y));
}

__device__ __forceinline__ uint2 cvt_f4_h4(float4 v) {
    __half2 h0 = __floats2half2_rn(v.x, v.y);
    __half2 h1 = __floats2half2_rn(v.z, v.w);
    uint2 u;
    u.x = *reinterpret_cast<uint32_t*>(&h0);
    u.y = *reinterpret_cast<uint32_t*>(&h1);
    return u;
}

// ---------------------------------------------------------------------------
// fused prep: conv_x | conv_w | bias in one launch (block-range split)
// ---------------------------------------------------------------------------
__global__ void prep_kernel(const float* __restrict__ x,
                            const float* __restrict__ W1,
                            const float* __restrict__ day_emb,
                            const float* __restrict__ b1) {
    int blk = blockIdx.x;
    int tid = threadIdx.x;

    if (blk < XBLKS) {
        // ---- conv_x: fp32 -> fp16 (kept cacheable: gemm re-reads x) ----
        int i = blk * 256 + tid;
        float4 v = reinterpret_cast<const float4*>(x)[i];
        reinterpret_cast<uint2*>(g_xh)[i] = cvt_f4_h4(v);
    } else if (blk < XBLKS + WBLKS) {
        // ---- conv_w: 2 float4/thread; W1[p] rows 0..1023 are CONTIGUOUS ----
        long long i0 = ((long long)(blk - XBLKS) * 256 + tid) * 2;   // float4 idx
        long long e = i0 * 4;                                        // float idx
        int p = (int)(e / ((long long)INPUT_DIM * HIDDEN));
        long long rem = e - (long long)p * INPUT_DIM * HIDDEN;
        const float* src = W1 + (size_t)p * W1_ROWS * HIDDEN + rem;
        float4 v0 = ldg_cs_f4(src);
        float4 v1 = ldg_cs_f4(src + 4);
        stg_cs_u2(reinterpret_cast<uint2*>(g_W1h) + i0,     cvt_f4_h4(v0));
        stg_cs_u2(reinterpret_cast<uint2*>(g_W1h) + i0 + 1, cvt_f4_h4(v1));
    } else {
        // ---- bias: c[p][h] = b1 + day_emb @ W1e ----
        int p = blk - XBLKS - WBLKS;
        const float* w = W1 + (size_t)p * W1_ROWS * HIDDEN + (size_t)INPUT_DIM * HIDDEN;
        #pragma unroll
        for (int hh = 0; hh < 2; ++hh) {
            int h = hh * 256 + tid;
            float s = b1[p * HIDDEN + h];
            #pragma unroll
            for (int e = 0; e < DAY_EMB; ++e)
                s += day_emb[p * DAY_EMB + e] * w[e * HIDDEN + h];
            g_bias[p * HIDDEN + h] = s;
        }
    }
}

// ---------------------------------------------------------------------------
// fused fp16 GEMM (x @ W1x[p]) + bias + ReLU + dot(W2[p]) -> partials
//   grid (NT, MT, PRED_LEN); 256 thr = 8 warps (4m x 2n), warp tile 32x64
//   BK=32, 4-stage cp.async (wait_group 2), ONE barrier/iter, 2 CTAs/SM
//   c-loop unrolled 8x; staging split A@kb0 / B@kb1; coalesced partials
// ---------------------------------------------------------------------------
__global__ void __launch_bounds__(THREADS, 2)
mlp_gemm_kernel(const float* __restrict__ W2) {
    extern __shared__ uint4 sm4[];                   // [STAGES][STG_I4]
    __shared__ float cs[BN], ws[BN], red[2][BM];

    const int nt = blockIdx.x, mt = blockIdx.y, p = blockIdx.z;
    const int tid = threadIdx.x, lane = tid & 31, warp = tid >> 5;
    const int wm = warp >> 1, wn = warp & 1;         // 4 x 2
    const int r = lane >> 2, cc = lane & 3;
    const int m0 = mt * BM, n0 = nt * BN;

    const uint32_t smb = smem_u32(sm4);

    // ---- cp.async staging mapping (BK=32) ----
    const int ra = tid >> 2, ca = tid & 3;           // A: rows ra, ra+64; i4 col ca
    const int rb = tid >> 3, cb = tid & 7;           // B: row rb; i4 cols cb, cb+8
    const __half* Agp = g_xh + (size_t)(m0 + ra) * INPUT_DIM + ca * 8;
    const __half* Bgp = g_W1h + ((size_t)p * INPUT_DIM + rb) * HIDDEN + n0 + cb * 8;

    auto issue_A = [&](int s, int c) {
        const uint32_t st = smb + (uint32_t)(s * STG_I4) * 16;
        const __half* ag = Agp + c * BK;
        CP_ASYNC16(st + (uint32_t)(ra * A_PI4 + ca) * 16, ag);
        CP_ASYNC16(st + (uint32_t)((ra + 64) * A_PI4 + ca) * 16, ag + (size_t)64 * INPUT_DIM);
    };
    auto issue_B = [&](int s, int c) {
        const uint32_t st = smb + (uint32_t)(s * STG_I4) * 16;
        const __half* bg = Bgp + (size_t)c * BK * HIDDEN;
        const uint32_t bst = st + (uint32_t)(A_I4 + rb * B_PI4 + cb) * 16;
        CP_ASYNC16(bst, bg);
        CP_ASYNC16(bst + 8 * 16, bg + 64);
    };

    // start the pipeline first
    issue_A(0, 0); issue_B(0, 0); CP_COMMIT();
    issue_A(1, 1); issue_B(1, 1); CP_COMMIT();
    issue_A(2, 2); issue_B(2, 2); CP_COMMIT();

    if (tid < BN) {
        cs[tid] = g_bias[p * HIDDEN + n0 + tid];
        ws[tid] = W2[p * HIDDEN + n0 + tid];
    }

    float acc[2][8][4];
    #pragma unroll
    for (int mi = 0; mi < 2; ++mi)
        #pragma unroll
        for (int ni = 0; ni < 8; ++ni)
            #pragma unroll
            for (int q = 0; q < 4; ++q) acc[mi][ni][q] = 0.0f;

    const int lrow = lane & 15, lhi = lane >> 4;

    #pragma unroll 8
    for (int c = 0; c < KCH; ++c) {
        const int s = c & 3;
        CP_WAIT2();
        __syncthreads();                 // single barrier per iteration

        const uint32_t Ab = smb + (uint32_t)(s * STG_I4) * 16;
        const uint32_t Bb = Ab + (uint32_t)A_I4 * 16;
        #pragma unroll
        for (int kb = 0; kb < 2; ++kb) {
            uint32_t a[2][4], b[4][4];
            #pragma unroll
            for (int mi = 0; mi < 2; ++mi) {
                uint32_t addr = Ab + (uint32_t)((wm * 32 + mi * 16 + lrow) * A_PI4 + kb * 2 + lhi) * 16;
                LDMX4(a[mi][0], a[mi][1], a[mi][2], a[mi][3], addr);
            }
            #pragma unroll
            for (int nj = 0; nj < 4; ++nj) {
                uint32_t addr = Bb + (uint32_t)((kb * 16 + lrow) * B_PI4) * 16
                              + (uint32_t)(wn * 128 + nj * 32 + lhi * 16);
                LDMX4T(b[nj][0], b[nj][1], b[nj][2], b[nj][3], addr);
            }
            // spread staging: A at kb=0, B + commit at kb=1
            if (kb == 0) {
                if (c + 3 < KCH) issue_A((c + 3) & 3, c + 3);
            } else {
                if (c + 3 < KCH) issue_B((c + 3) & 3, c + 3);
                CP_COMMIT();
            }
            #pragma unroll
            for (int mi = 0; mi < 2; ++mi)
                #pragma unroll
                for (int ni = 0; ni < 8; ++ni) {
                    const uint32_t* bp = b[ni >> 1];
                    uint32_t b0 = (ni & 1) ? bp[2] : bp[0];
                    uint32_t b1 = (ni & 1) ? bp[3] : bp[1];
                    mma_f16(acc[mi][ni], a[mi], b0, b1);
                }
        }
    }

    __syncthreads();

    // ---- fused epilogue: bias + relu + W2 dot, reduce over n ----
    #pragma unroll
    for (int mi = 0; mi < 2; ++mi) {
        float rs0 = 0.0f, rs1 = 0.0f;
        #pragma unroll
        for (int ni = 0; ni < 8; ++ni) {
            int col = wn * 64 + ni * 8 + cc * 2;
            float h0 = acc[mi][ni][0] + cs[col];
            float h1 = acc[mi][ni][1] + cs[col + 1];
            float h2 = acc[mi][ni][2] + cs[col];
            float h3 = acc[mi][ni][3] + cs[col + 1];
            rs0 += fmaxf(h0, 0.0f) * ws[col] + fmaxf(h1, 0.0f) * ws[col + 1];
            rs1 += fmaxf(h2, 0.0f) * ws[col] + fmaxf(h3, 0.0f) * ws[col + 1];
        }
        #pragma unroll
        for (int off = 1; off < 4; off <<= 1) {
            rs0 += __shfl_xor_sync(0xffffffffu, rs0, off);
            rs1 += __shfl_xor_sync(0xffffffffu, rs1, off);
        }
        if ((lane & 3) == 0) {
            int row = wm * 32 + mi * 16 + r;
            red[wn][row]     = rs0;
            red[wn][row + 8] = rs1;
        }
    }
    __syncthreads();

    if (tid < BM) {
        float v = red[0][tid] + red[1][tid];
        // [nt][p][b] layout: consecutive tid -> consecutive addresses
        g_part[((size_t)nt * PRED_LEN + p) * BATCH + m0 + tid] = v;
    }
}

// ---------------------------------------------------------------------------
// reduce partials + b2 -> out[b][p]; smem transpose for coalescing
//   grid (BATCH/128, PRED_LEN/8), 256 threads
// ---------------------------------------------------------------------------
__global__ void reduce_kernel(const float* __restrict__ b2, float* __restrict__ out) {
    __shared__ float sm[8][129];
    const int b0 = blockIdx.x * 128;
    const int p0 = blockIdx.y * 8;
    const int tid = threadIdx.x;
    const int bl = tid & 127;            // b within tile
    const int ph = tid >> 7;             // 0..1

    #pragma unroll
    for (int pi = 0; pi < 4; ++pi) {
        int pl = ph + pi * 2;            // p within tile
        int p = p0 + pl;
        float s = b2[p];
        #pragma unroll
        for (int nt = 0; nt < NT; ++nt)
            s += g_part[((size_t)nt * PRED_LEN + p) * BATCH + b0 + bl];
        sm[pl][bl] = s;
    }
    __syncthreads();

    const int pw = tid & 7;              // p within tile (write phase)
    const int bw = tid >> 3;             // b base (32 per pass)
    #pragma unroll
    for (int w = 0; w < 4; ++w) {
        int bb = bw + w * 32;
        out[(size_t)(b0 + bb) * PRED_LEN + p0 + pw] = sm[pw][bb];
    }
}

// ---------------------------------------------------------------------------
extern "C" void kernel_launch(void* const* d_in, const int* in_sizes, int n_in,
                              void* d_out, int out_size) {
    const float* x       = (const float*)d_in[0];
    const float* day_emb = (const float*)d_in[1];
    const float* W1      = (const float*)d_in[2];
    const float* b1      = (const float*)d_in[3];
    const float* W2      = (const float*)d_in[4];
    const float* b2      = (const float*)d_in[5];
    float* out = (float*)d_out;

    const int SMEM = STAGES * STG_I4 * 16;   // 75776 bytes
    cudaFuncSetAttribute(mlp_gemm_kernel,
                         cudaFuncAttributeMaxDynamicSharedMemorySize, SMEM);

    prep_kernel<<<PREP_BLKS, 256>>>(x, W1, day_emb, b1);

    dim3 grid(NT, MT, PRED_LEN);
    mlp_gemm_kernel<<<grid, THREADS, SMEM>>>(W2);

    dim3 rgrid(BATCH / 128, PRED_LEN / 8);
    reduce_kernel<<<rgrid, 256>>>(b2, out);
}